// round 2
// baseline (speedup 1.0000x reference)
#include <cuda_runtime.h>
#include <math.h>

// Problem constants
// E=2 streams, B=8, H=W=64, C=64, DI=128, L=4096, K=4 dirs, R=4, N=1
#define EB 16            // E*B
#define L_ 4096
#define DI_ 128
#define C_ 64
#define NROW 65536       // E*B*L rows

// ---------------- scratch (static __device__, no allocation) ----------------
__device__ float g_xcpre[EB * L_ * DI_];   // pre-conv x branch [eb][s][d]
__device__ float g_z    [EB * L_ * DI_];   // silu(z)           [eb][s][d]
__device__ float g_xc   [EB * L_ * DI_];   // conv+silu output  [eb][s][d]
__device__ float g_xcT  [EB * DI_ * L_];   // [eb][d][s]
__device__ float g_xcT2 [EB * DI_ * L_];   // [eb][d][j], j = transposed-spatial order
__device__ float g_rec  [EB * 4 * L_ * 8]; // per (eb,k,j): dt0..3, Bs, Cs, pad2
__device__ float g_ys   [EB * 4 * DI_ * L_]; // scan out, spatial order [eb][k][d][s]
__device__ float g_y    [EB * L_ * DI_];   // merged y [eb][s][d]
__device__ float g_xres [EB * L_ * C_];    // residual after attention part
__device__ float g_mlp  [EB * L_ * C_];    // per-stream final output

__device__ __forceinline__ int ltmap(int j) { return ((j & 63) << 6) | (j >> 6); }

__device__ __forceinline__ float siluf(float v) {
    return v / (1.f + expf(-v));
}
__device__ __forceinline__ float softplusf(float x) {
    float r = log1pf(__expf(x));
    return (x > 15.f) ? x : r;
}
__device__ __forceinline__ float geluf(float v) {
    return 0.5f * v * (1.f + erff(v * 0.70710678118654752f));
}

// ---------------- K1: LN + in_proj (64 -> 256), split, silu(z) --------------
__global__ void k1_ln_inproj(const float* __restrict__ mag, const float* __restrict__ phase,
                             const float* __restrict__ n1w, const float* __restrict__ n1b,
                             const float* __restrict__ wproj)
{
    __shared__ float sx[32][64];
    __shared__ float smu[32], srs[32];
    int row0 = blockIdx.x * 32;          // global row (e*32768 + b*4096 + s)
    int e = row0 >> 15;
    const float* xin = e ? phase : mag;
    int rloc0 = row0 & 32767;
    int t = threadIdx.x;
    int r = t >> 3, c0 = (t & 7) * 8;
    {
        float4 v0 = *(const float4*)&xin[(rloc0 + r) * 64 + c0];
        float4 v1 = *(const float4*)&xin[(rloc0 + r) * 64 + c0 + 4];
        sx[r][c0+0]=v0.x; sx[r][c0+1]=v0.y; sx[r][c0+2]=v0.z; sx[r][c0+3]=v0.w;
        sx[r][c0+4]=v1.x; sx[r][c0+5]=v1.y; sx[r][c0+6]=v1.z; sx[r][c0+7]=v1.w;
    }
    __syncthreads();
    if (t < 32) {
        float s = 0.f, s2 = 0.f;
        #pragma unroll
        for (int i = 0; i < 64; i++) { float v = sx[t][i]; s += v; s2 += v * v; }
        float mu = s * (1.f / 64.f);
        smu[t] = mu;
        srs[t] = rsqrtf(fmaxf(s2 * (1.f / 64.f) - mu * mu, 0.f) + 1e-5f);
    }
    __syncthreads();
    {
        float mu = smu[r], rs = srs[r];
        #pragma unroll
        for (int i = 0; i < 8; i++) {
            int c = c0 + i;
            sx[r][c] = (sx[r][c] - mu) * rs * n1w[e * 64 + c] + n1b[e * 64 + c];
        }
    }
    __syncthreads();
    float acc[32];
    #pragma unroll
    for (int i = 0; i < 32; i++) acc[i] = 0.f;
    const float4* wp = (const float4*)&wproj[(e * 256 + t) * 64];
    for (int ch = 0; ch < 16; ch++) {
        float4 w4 = wp[ch];
        #pragma unroll
        for (int rr = 0; rr < 32; rr++) {
            acc[rr] = fmaf(w4.x, sx[rr][ch*4+0], acc[rr]);
            acc[rr] = fmaf(w4.y, sx[rr][ch*4+1], acc[rr]);
            acc[rr] = fmaf(w4.z, sx[rr][ch*4+2], acc[rr]);
            acc[rr] = fmaf(w4.w, sx[rr][ch*4+3], acc[rr]);
        }
    }
    if (t < 128) {
        #pragma unroll
        for (int rr = 0; rr < 32; rr++)
            g_xcpre[(row0 + rr) * 128 + t] = acc[rr];
    } else {
        int c = t - 128;
        #pragma unroll
        for (int rr = 0; rr < 32; rr++)
            g_z[(row0 + rr) * 128 + c] = siluf(acc[rr]);
    }
}

// ---------------- K2: depthwise 3x3 conv + silu -----------------------------
__global__ void k2_conv(const float* __restrict__ cw)
{
    int row = blockIdx.x;            // eb*4096 + s
    int d = threadIdx.x;             // 0..127
    int s = row & 4095;
    int eb = row >> 12;
    int e = eb >> 3;
    int h = s >> 6, w = s & 63;
    const float* base = &g_xcpre[eb * 4096 * 128];
    const float* wk = &cw[(e * 128 + d) * 9];
    float acc = 0.f;
    #pragma unroll
    for (int ky = 0; ky < 3; ky++) {
        int hh = h + ky - 1;
        if ((unsigned)hh < 64u) {
            #pragma unroll
            for (int kx = 0; kx < 3; kx++) {
                int ww = w + kx - 1;
                if ((unsigned)ww < 64u)
                    acc = fmaf(base[(hh * 64 + ww) * 128 + d], wk[ky * 3 + kx], acc);
            }
        }
    }
    g_xc[row * 128 + d] = siluf(acc);
}

// ---------------- KT: build [d][s] and [d][sT] layouts ----------------------
__global__ void k_transpose()
{
    __shared__ float tile[32][33];
    int which = blockIdx.z;
    int jt = blockIdx.x * 32;
    int dt = (blockIdx.y & 3) * 32;
    int eb = blockIdx.y >> 2;
    int tx = threadIdx.x, ty = threadIdx.y;   // (32, 8)
    #pragma unroll
    for (int i = 0; i < 4; i++) {
        int j = jt + ty + 8 * i;
        int s = which ? ltmap(j) : j;
        tile[ty + 8 * i][tx] = g_xc[(eb * 4096 + s) * 128 + dt + tx];
    }
    __syncthreads();
    float* out = which ? g_xcT2 : g_xcT;
    #pragma unroll
    for (int i = 0; i < 4; i++)
        out[(eb * 128 + dt + ty + 8 * i) * 4096 + jt + tx] = tile[tx][ty + 8 * i];
}

// ---------------- K3: x_proj (128 -> 6) per direction/position --------------
__global__ void k3_xdbl(const float* __restrict__ xprojw)
{
    int wid = (blockIdx.x << 3) + (threadIdx.x >> 5);  // 0..262143
    int lane = threadIdx.x & 31;
    int j = wid & 4095;
    int k = (wid >> 12) & 3;
    int b = (wid >> 14) & 7;
    int e = wid >> 17;
    int jj = (k >= 2) ? 4095 - j : j;
    int pos = (k & 1) ? ltmap(jj) : jj;
    const float4* xv = (const float4*)&g_xc[((e * 8 + b) * 4096 + pos) * 128];
    float4 x4 = xv[lane];
    const float4* wb = (const float4*)&xprojw[((e * 4 + k) * 6) * 128];
    float dot[6];
    #pragma unroll
    for (int c = 0; c < 6; c++) {
        float4 w4 = wb[c * 32 + lane];
        dot[c] = x4.x * w4.x + x4.y * w4.y + x4.z * w4.z + x4.w * w4.w;
    }
    #pragma unroll
    for (int off = 16; off > 0; off >>= 1) {
        #pragma unroll
        for (int c = 0; c < 6; c++)
            dot[c] += __shfl_xor_sync(0xffffffffu, dot[c], off);
    }
    if (lane == 0) {
        float* rp = &g_rec[(((e * 8 + b) * 4 + k) * 4096 + j) * 8];
        *(float4*)rp       = make_float4(dot[0], dot[1], dot[2], dot[3]);
        *(float4*)(rp + 4) = make_float4(dot[4], dot[5], 0.f, 0.f);
    }
}

// ---------------- K4: selective scan (chunked + block combine) --------------
__global__ void k4_scan(const float* __restrict__ dtw, const float* __restrict__ dtb,
                        const float* __restrict__ alogs, const float* __restrict__ dsv)
{
    __shared__ __align__(16) float sD[4096];
    __shared__ __align__(16) float sY[4096];
    __shared__ float scA[128], scB[128];
    int blk = blockIdx.x;                 // ((e*8+b)*4+k)*128 + d
    int d = blk & 127, k = (blk >> 7) & 3, b = (blk >> 9) & 7, e = blk >> 12;
    int t = threadIdx.x;                  // 0..127
    int kd = (e * 4 + k) * 128 + d;
    float4 w4 = *(const float4*)&dtw[kd * 4];
    float bias = dtb[kd];
    float Aval = -expf(alogs[e * 512 + k * 128 + d]);
    float Dval = dsv[e * 512 + k * 128 + d];
    const float* xsrc = ((k & 1) ? g_xcT2 : g_xcT) + ((e * 8 + b) * 128 + d) * 4096;
    int rev = (k >= 2);
    const float* rec = &g_rec[(((e * 8 + b) * 4 + k) * 4096) * 8];
    float Ap = 1.f, Bp = 0.f;
    int j0 = t * 32;
    for (int i = 0; i < 32; i++) {
        int j = j0 + i;
        float xsv = xsrc[rev ? 4095 - j : j];
        const float* rp = rec + j * 8;
        float4 dt4 = *(const float4*)rp;
        float Bs = rp[4];
        float zz = fmaf(w4.x, dt4.x, fmaf(w4.y, dt4.y, fmaf(w4.z, dt4.z, fmaf(w4.w, dt4.w, bias))));
        float delta = softplusf(zz);
        sD[i * 128 + t] = delta;
        float a = __expf(delta * Aval);
        float bb = delta * Bs * xsv;
        Ap *= a;
        Bp = fmaf(Bp, a, bb);
    }
    scA[t] = Ap; scB[t] = Bp;
    __syncthreads();
    for (int off = 1; off < 128; off <<= 1) {
        float a1 = 1.f, b1 = 0.f;
        if (t >= off) { a1 = scA[t - off]; b1 = scB[t - off]; }
        float a2 = scA[t], b2 = scB[t];
        __syncthreads();
        scA[t] = a1 * a2;
        scB[t] = fmaf(b1, a2, b2);
        __syncthreads();
    }
    float h = (t == 0) ? 0.f : scB[t - 1];
    for (int i = 0; i < 32; i++) {
        int j = j0 + i;
        float delta = sD[i * 128 + t];
        float a = __expf(delta * Aval);
        const float* rp = rec + j * 8;
        float Bs = rp[4], Cs = rp[5];
        float xsv = xsrc[rev ? 4095 - j : j];
        float bb = delta * Bs * xsv;
        h = fmaf(a, h, bb);
        float ys = fmaf(h, Cs, Dval * xsv);
        int jm = rev ? 4095 - j : j;
        int mp = (k & 1) ? ltmap(jm) : jm;   // spatial position
        sY[mp] = ys;
    }
    __syncthreads();
    float4* yo = (float4*)&g_ys[(size_t)blk * 4096];
    const float4* ysm = (const float4*)sY;
    #pragma unroll
    for (int rr = 0; rr < 8; rr++)
        yo[rr * 128 + t] = ysm[rr * 128 + t];
}

// ---------------- K5: merge 4 directions + transpose to [s][d] --------------
__global__ void k5_combine()
{
    __shared__ float tile[32][33];
    int st = blockIdx.x * 32;
    int dt = (blockIdx.y & 3) * 32;
    int eb = blockIdx.y >> 2;
    int tx = threadIdx.x, ty = threadIdx.y;   // (32, 8)
    #pragma unroll
    for (int i = 0; i < 4; i++) {
        int dd = dt + ty + 8 * i;
        const float* p = &g_ys[(size_t)((eb * 4) * 128 + dd) * 4096 + st + tx];
        float v = p[0] + p[128 * 4096] + p[2 * 128 * 4096] + p[3 * 128 * 4096];
        tile[ty + 8 * i][tx] = v;
    }
    __syncthreads();
    #pragma unroll
    for (int i = 0; i < 4; i++)
        g_y[(eb * 4096 + st + ty + 8 * i) * 128 + dt + tx] = tile[tx][ty + 8 * i];
}

// ---------------- K6: out LN * z, out_proj (128 -> 64), + residual ----------
__global__ void k6_out(const float* __restrict__ mag, const float* __restrict__ phase,
                       const float* __restrict__ onw, const float* __restrict__ onb,
                       const float* __restrict__ opw)
{
    __shared__ float sx[32][128];
    __shared__ float smu[32], srs[32];
    int row0 = blockIdx.x * 32;
    int e = row0 >> 15;
    int t = threadIdx.x;
    int r = t >> 3, c0 = (t & 7) * 16;
    #pragma unroll
    for (int i = 0; i < 4; i++) {
        float4 v = *(const float4*)&g_y[(row0 + r) * 128 + c0 + 4 * i];
        sx[r][c0 + 4*i + 0] = v.x; sx[r][c0 + 4*i + 1] = v.y;
        sx[r][c0 + 4*i + 2] = v.z; sx[r][c0 + 4*i + 3] = v.w;
    }
    __syncthreads();
    if (t < 32) {
        float s = 0.f, s2 = 0.f;
        #pragma unroll 8
        for (int i = 0; i < 128; i++) { float v = sx[t][i]; s += v; s2 += v * v; }
        float mu = s * (1.f / 128.f);
        smu[t] = mu;
        srs[t] = rsqrtf(fmaxf(s2 * (1.f / 128.f) - mu * mu, 0.f) + 1e-5f);
    }
    __syncthreads();
    {
        float mu = smu[r], rs = srs[r];
        #pragma unroll
        for (int i = 0; i < 16; i++) {
            int c = c0 + i;
            float yn = (sx[r][c] - mu) * rs * onw[e * 128 + c] + onb[e * 128 + c];
            sx[r][c] = yn * g_z[(row0 + r) * 128 + c];
        }
    }
    __syncthreads();
    int c = t & 63, g = t >> 6;
    float acc[8];
    #pragma unroll
    for (int i = 0; i < 8; i++) acc[i] = 0.f;
    const float4* wp = (const float4*)&opw[(e * 64 + c) * 128];
    for (int ch = 0; ch < 32; ch++) {
        float4 w4 = wp[ch];
        #pragma unroll
        for (int rr = 0; rr < 8; rr++) {
            int r2 = g * 8 + rr;
            acc[rr] = fmaf(w4.x, sx[r2][ch*4+0], acc[rr]);
            acc[rr] = fmaf(w4.y, sx[r2][ch*4+1], acc[rr]);
            acc[rr] = fmaf(w4.z, sx[r2][ch*4+2], acc[rr]);
            acc[rr] = fmaf(w4.w, sx[r2][ch*4+3], acc[rr]);
        }
    }
    const float* xin = e ? phase : mag;
    int rl0 = row0 & 32767;
    #pragma unroll
    for (int rr = 0; rr < 8; rr++) {
        int r2 = g * 8 + rr;
        g_xres[(row0 + r2) * 64 + c] = acc[rr] + xin[(rl0 + r2) * 64 + c];
    }
}

// ---------------- K7: LN + fc1 + gelu + fc2 + residual ----------------------
__global__ void k7_mlp(const float* __restrict__ n2w, const float* __restrict__ n2b,
                       const float* __restrict__ f1w, const float* __restrict__ f1b,
                       const float* __restrict__ f2w, const float* __restrict__ f2b)
{
    __shared__ float sx[32][64];
    __shared__ float sh[32][256];
    __shared__ float smu[32], srs[32];
    int row0 = blockIdx.x * 32;
    int e = row0 >> 15;
    int t = threadIdx.x;
    int r = t >> 3, c0 = (t & 7) * 8;
    {
        float4 v0 = *(const float4*)&g_xres[(row0 + r) * 64 + c0];
        float4 v1 = *(const float4*)&g_xres[(row0 + r) * 64 + c0 + 4];
        sx[r][c0+0]=v0.x; sx[r][c0+1]=v0.y; sx[r][c0+2]=v0.z; sx[r][c0+3]=v0.w;
        sx[r][c0+4]=v1.x; sx[r][c0+5]=v1.y; sx[r][c0+6]=v1.z; sx[r][c0+7]=v1.w;
    }
    __syncthreads();
    if (t < 32) {
        float s = 0.f, s2 = 0.f;
        #pragma unroll
        for (int i = 0; i < 64; i++) { float v = sx[t][i]; s += v; s2 += v * v; }
        float mu = s * (1.f / 64.f);
        smu[t] = mu;
        srs[t] = rsqrtf(fmaxf(s2 * (1.f / 64.f) - mu * mu, 0.f) + 1e-5f);
    }
    __syncthreads();
    {
        float mu = smu[r], rs = srs[r];
        #pragma unroll
        for (int i = 0; i < 8; i++) {
            int c = c0 + i;
            sx[r][c] = (sx[r][c] - mu) * rs * n2w[e * 64 + c] + n2b[e * 64 + c];
        }
    }
    __syncthreads();
    // fc1: each thread owns one hidden channel t (0..255)
    {
        float acc[32];
        #pragma unroll
        for (int i = 0; i < 32; i++) acc[i] = 0.f;
        const float4* wp = (const float4*)&f1w[(e * 256 + t) * 64];
        for (int ch = 0; ch < 16; ch++) {
            float4 w4 = wp[ch];
            #pragma unroll
            for (int rr = 0; rr < 32; rr++) {
                acc[rr] = fmaf(w4.x, sx[rr][ch*4+0], acc[rr]);
                acc[rr] = fmaf(w4.y, sx[rr][ch*4+1], acc[rr]);
                acc[rr] = fmaf(w4.z, sx[rr][ch*4+2], acc[rr]);
                acc[rr] = fmaf(w4.w, sx[rr][ch*4+3], acc[rr]);
            }
        }
        float b1 = f1b[e * 256 + t];
        #pragma unroll
        for (int rr = 0; rr < 32; rr++)
            sh[rr][t] = geluf(acc[rr] + b1);
    }
    __syncthreads();
    // fc2: c = t&63, rows split by g = t>>6
    {
        int c = t & 63, g = t >> 6;
        float acc[8];
        #pragma unroll
        for (int i = 0; i < 8; i++) acc[i] = 0.f;
        const float4* wp = (const float4*)&f2w[(e * 64 + c) * 256];
        for (int ch = 0; ch < 64; ch++) {
            float4 w4 = wp[ch];
            #pragma unroll
            for (int rr = 0; rr < 8; rr++) {
                int r2 = g * 8 + rr;
                acc[rr] = fmaf(w4.x, sh[r2][ch*4+0], acc[rr]);
                acc[rr] = fmaf(w4.y, sh[r2][ch*4+1], acc[rr]);
                acc[rr] = fmaf(w4.z, sh[r2][ch*4+2], acc[rr]);
                acc[rr] = fmaf(w4.w, sh[r2][ch*4+3], acc[rr]);
            }
        }
        float b2 = f2b[e * 64 + c];
        #pragma unroll
        for (int rr = 0; rr < 8; rr++) {
            int r2 = g * 8 + rr;
            g_mlp[(row0 + r2) * 64 + c] = g_xres[(row0 + r2) * 64 + c] + acc[rr] + b2;
        }
    }
}

// ---------------- K8: sum streams, duplicate output -------------------------
__global__ void k8_final(float* __restrict__ out)
{
    int i = blockIdx.x * 256 + threadIdx.x;   // 0..2097151
    float s = g_mlp[i] + g_mlp[i + 2097152];
    out[i] = s;
    out[i + 2097152] = s;
}

// ---------------- launch ----------------------------------------------------
extern "C" void kernel_launch(void* const* d_in, const int* in_sizes, int n_in,
                              void* d_out, int out_size)
{
    const float* mag   = (const float*)d_in[0];
    const float* phase = (const float*)d_in[1];
    const float* n1w   = (const float*)d_in[2];
    const float* n1b   = (const float*)d_in[3];
    const float* ipw   = (const float*)d_in[4];
    const float* cvw   = (const float*)d_in[5];
    const float* xpw   = (const float*)d_in[6];
    const float* dtw   = (const float*)d_in[7];
    const float* dtb   = (const float*)d_in[8];
    const float* alg   = (const float*)d_in[9];
    const float* dsv   = (const float*)d_in[10];
    const float* onw   = (const float*)d_in[11];
    const float* onb   = (const float*)d_in[12];
    const float* opw   = (const float*)d_in[13];
    const float* n2w   = (const float*)d_in[14];
    const float* n2b   = (const float*)d_in[15];
    const float* f1w   = (const float*)d_in[16];
    const float* f1b   = (const float*)d_in[17];
    const float* f2w   = (const float*)d_in[18];
    const float* f2b   = (const float*)d_in[19];

    k1_ln_inproj<<<2048, 256>>>(mag, phase, n1w, n1b, ipw);
    k2_conv<<<65536, 128>>>(cvw);
    k_transpose<<<dim3(128, 64, 2), dim3(32, 8)>>>();
    k3_xdbl<<<32768, 256>>>(xpw);
    k4_scan<<<8192, 128>>>(dtw, dtb, alg, dsv);
    k5_combine<<<dim3(128, 64), dim3(32, 8)>>>();
    k6_out<<<2048, 256>>>(mag, phase, onw, onb, opw);
    k7_mlp<<<2048, 256>>>(n2w, n2b, f1w, f1b, f2w, f2b);
    k8_final<<<8192, 256>>>((float*)d_out);
}

// round 4
// speedup vs baseline: 3.2859x; 3.2859x over previous
#include <cuda_runtime.h>
#include <math.h>

// Problem constants
// E=2 streams, B=8, H=W=64, C=64, DI=128, L=4096, K=4 dirs, R=4, N=1
#define EB 16            // E*B
#define L_ 4096
#define DI_ 128
#define C_ 64
#define CH 32            // scan chunks per sequence
#define CLEN 128         // chunk length (CH*CLEN = L)

// ---------------- scratch (static __device__, no allocation) ----------------
__device__ float g_xcpre[EB * L_ * DI_];     // pre-conv x branch [eb][s][d]
__device__ float g_z    [EB * L_ * DI_];     // silu(z)           [eb][s][d]
__device__ float g_xc   [EB * L_ * DI_];     // conv+silu output  [eb][s][d]
__device__ float g_rec  [EB * 4 * L_ * 8];   // per (eb,k,j): dt0..3, Bs, Cs, pad2
__device__ float g_aggA [64 * CH * DI_];     // chunk aggregate A
__device__ float g_aggB [64 * CH * DI_];     // chunk aggregate B
__device__ float g_pref [64 * CH * DI_];     // incoming prefix per chunk
__device__ float g_ys   [4 * EB * L_ * DI_]; // scan out, 4 planes, spatial [s][d]
__device__ float g_xres [EB * L_ * C_];      // residual after attention part
__device__ float g_mlp  [EB * L_ * C_];      // per-stream final output

__device__ __forceinline__ int ltmap(int j) { return ((j & 63) << 6) | (j >> 6); }

__device__ __forceinline__ float siluf(float v) {
    return v / (1.f + expf(-v));
}
__device__ __forceinline__ float sp(float x) {   // softplus, stable + fast
    return fmaxf(x, 0.f) + __logf(1.f + __expf(-fabsf(x)));
}
__device__ __forceinline__ float geluf(float v) {
    return 0.5f * v * (1.f + erff(v * 0.70710678118654752f));
}

// ---------------- K1: LN + in_proj (64 -> 256), split, silu(z) --------------
__global__ void k1_ln_inproj(const float* __restrict__ mag, const float* __restrict__ phase,
                             const float* __restrict__ n1w, const float* __restrict__ n1b,
                             const float* __restrict__ wproj)
{
    __shared__ float sx[32][64];
    __shared__ float smu[32], srs[32];
    int row0 = blockIdx.x * 32;          // global row (e*32768 + b*4096 + s)
    int e = row0 >> 15;
    const float* xin = e ? phase : mag;
    int rloc0 = row0 & 32767;
    int t = threadIdx.x;
    int r = t >> 3, c0 = (t & 7) * 8;
    {
        float4 v0 = *(const float4*)&xin[(rloc0 + r) * 64 + c0];
        float4 v1 = *(const float4*)&xin[(rloc0 + r) * 64 + c0 + 4];
        sx[r][c0+0]=v0.x; sx[r][c0+1]=v0.y; sx[r][c0+2]=v0.z; sx[r][c0+3]=v0.w;
        sx[r][c0+4]=v1.x; sx[r][c0+5]=v1.y; sx[r][c0+6]=v1.z; sx[r][c0+7]=v1.w;
    }
    __syncthreads();
    if (t < 32) {
        float s = 0.f, s2 = 0.f;
        #pragma unroll
        for (int i = 0; i < 64; i++) { float v = sx[t][i]; s += v; s2 += v * v; }
        float mu = s * (1.f / 64.f);
        smu[t] = mu;
        srs[t] = rsqrtf(fmaxf(s2 * (1.f / 64.f) - mu * mu, 0.f) + 1e-5f);
    }
    __syncthreads();
    {
        float mu = smu[r], rs = srs[r];
        #pragma unroll
        for (int i = 0; i < 8; i++) {
            int c = c0 + i;
            sx[r][c] = (sx[r][c] - mu) * rs * n1w[e * 64 + c] + n1b[e * 64 + c];
        }
    }
    __syncthreads();
    float acc[32];
    #pragma unroll
    for (int i = 0; i < 32; i++) acc[i] = 0.f;
    const float4* wp = (const float4*)&wproj[(e * 256 + t) * 64];
    for (int ch = 0; ch < 16; ch++) {
        float4 w4 = wp[ch];
        #pragma unroll
        for (int rr = 0; rr < 32; rr++) {
            acc[rr] = fmaf(w4.x, sx[rr][ch*4+0], acc[rr]);
            acc[rr] = fmaf(w4.y, sx[rr][ch*4+1], acc[rr]);
            acc[rr] = fmaf(w4.z, sx[rr][ch*4+2], acc[rr]);
            acc[rr] = fmaf(w4.w, sx[rr][ch*4+3], acc[rr]);
        }
    }
    if (t < 128) {
        #pragma unroll
        for (int rr = 0; rr < 32; rr++)
            g_xcpre[(row0 + rr) * 128 + t] = acc[rr];
    } else {
        int c = t - 128;
        #pragma unroll
        for (int rr = 0; rr < 32; rr++)
            g_z[(row0 + rr) * 128 + c] = siluf(acc[rr]);
    }
}

// ---------------- K2: depthwise 3x3 conv + silu -----------------------------
__global__ void k2_conv(const float* __restrict__ cw)
{
    int row = blockIdx.x;            // eb*4096 + s
    int d = threadIdx.x;             // 0..127
    int s = row & 4095;
    int eb = row >> 12;
    int e = eb >> 3;
    int h = s >> 6, w = s & 63;
    const float* base = &g_xcpre[eb * 4096 * 128];
    const float* wk = &cw[(e * 128 + d) * 9];
    float acc = 0.f;
    #pragma unroll
    for (int ky = 0; ky < 3; ky++) {
        int hh = h + ky - 1;
        if ((unsigned)hh < 64u) {
            #pragma unroll
            for (int kx = 0; kx < 3; kx++) {
                int ww = w + kx - 1;
                if ((unsigned)ww < 64u)
                    acc = fmaf(base[(hh * 64 + ww) * 128 + d], wk[ky * 3 + kx], acc);
            }
        }
    }
    g_xc[row * 128 + d] = siluf(acc);
}

// ---------------- K3: x_proj (128 -> 6), 8 positions per warp ---------------
__global__ void k3_xdbl(const float* __restrict__ xprojw)
{
    int wid = blockIdx.x * 8 + (threadIdx.x >> 5);  // 0..32767
    int lane = threadIdx.x & 31;
    int j0 = (wid & 511) * 8;
    int k = (wid >> 9) & 3;
    int b = (wid >> 11) & 7;
    int e = wid >> 14;
    const float* xb = g_xc + (size_t)(e * 8 + b) * 4096 * 128;
    float4 w[6];
    #pragma unroll
    for (int c = 0; c < 6; c++)
        w[c] = *(const float4*)&xprojw[(((e * 4 + k) * 6) + c) * 128 + lane * 4];
    float* rbase = g_rec + (size_t)((e * 8 + b) * 4 + k) * 4096 * 8;
    #pragma unroll
    for (int p = 0; p < 8; p++) {
        int j = j0 + p;
        int jj = (k >= 2) ? 4095 - j : j;
        int pos = (k & 1) ? ltmap(jj) : jj;
        float4 x4 = *(const float4*)&xb[pos * 128 + lane * 4];
        float dot[6];
        #pragma unroll
        for (int c = 0; c < 6; c++)
            dot[c] = x4.x * w[c].x + x4.y * w[c].y + x4.z * w[c].z + x4.w * w[c].w;
        #pragma unroll
        for (int off = 16; off > 0; off >>= 1) {
            #pragma unroll
            for (int c = 0; c < 6; c++)
                dot[c] += __shfl_xor_sync(0xffffffffu, dot[c], off);
        }
        if (lane == 0) {
            float* rp = rbase + j * 8;
            *(float4*)rp       = make_float4(dot[0], dot[1], dot[2], dot[3]);
            *(float4*)(rp + 4) = make_float4(dot[4], dot[5], 0.f, 0.f);
        }
    }
}

// ---------------- K4a: scan pass 1 — per-chunk aggregates -------------------
// block = (ebk, chunk), thread = d. All threads share j per step:
// rec loads are uniform, x loads are coalesced 512B rows.
__global__ void k4a_scan_partial(const float* __restrict__ dtw, const float* __restrict__ dtb,
                                 const float* __restrict__ alogs)
{
    int blk = blockIdx.x;                 // ebk*CH + c
    int c = blk & (CH - 1);
    int ebk = blk >> 5;
    int k = ebk & 3, b = (ebk >> 2) & 7, e = ebk >> 5;
    int d = threadIdx.x;
    int kd = (e * 4 + k) * 128 + d;
    float4 w4 = *(const float4*)&dtw[kd * 4];
    float bias = dtb[kd];
    float Aval = -expf(alogs[kd]);
    const float* xb = g_xc + (size_t)(e * 8 + b) * 4096 * 128;
    const float* rec = g_rec + (size_t)((e * 8 + b) * 4 + k) * 4096 * 8;
    float Ap = 1.f, Bp = 0.f;
    int j0 = c * CLEN;
    #pragma unroll 4
    for (int i = 0; i < CLEN; i++) {
        int j = j0 + i;
        int jm = (k >= 2) ? 4095 - j : j;
        int pos = (k & 1) ? ltmap(jm) : jm;
        float4 r4 = *(const float4*)(rec + j * 8);
        float Bs = rec[j * 8 + 4];
        float x = xb[pos * 128 + d];
        float zz = fmaf(w4.x, r4.x, fmaf(w4.y, r4.y, fmaf(w4.z, r4.z, fmaf(w4.w, r4.w, bias))));
        float delta = sp(zz);
        float a = __expf(delta * Aval);
        float bb = delta * Bs * x;
        Ap *= a;
        Bp = fmaf(Bp, a, bb);
    }
    g_aggA[blk * 128 + d] = Ap;
    g_aggB[blk * 128 + d] = Bp;
}

// ---------------- K4b: scan pass 2 — prefix across chunks -------------------
__global__ void k4b_scan_prefix()
{
    int ebk = blockIdx.x;    // 0..63
    int d = threadIdx.x;
    float h = 0.f;
    #pragma unroll
    for (int c = 0; c < CH; c++) {
        int idx = (ebk * CH + c) * 128 + d;
        float A = g_aggA[idx], Bv = g_aggB[idx];
        g_pref[idx] = h;
        h = fmaf(A, h, Bv);
    }
}

// ---------------- K4c: scan pass 3 — apply prefix, write ys (spatial) -------
__global__ void k4c_scan_final(const float* __restrict__ dtw, const float* __restrict__ dtb,
                               const float* __restrict__ alogs, const float* __restrict__ dsv)
{
    int blk = blockIdx.x;
    int c = blk & (CH - 1);
    int ebk = blk >> 5;
    int k = ebk & 3, b = (ebk >> 2) & 7, e = ebk >> 5;
    int d = threadIdx.x;
    int kd = (e * 4 + k) * 128 + d;
    float4 w4 = *(const float4*)&dtw[kd * 4];
    float bias = dtb[kd];
    float Aval = -expf(alogs[kd]);
    float Dval = dsv[kd];
    int eb = e * 8 + b;
    const float* xb = g_xc + (size_t)eb * 4096 * 128;
    const float* rec = g_rec + (size_t)(eb * 4 + k) * 4096 * 8;
    float* yplane = g_ys + (size_t)(k * EB + eb) * 4096 * 128;
    float h = g_pref[blk * 128 + d];
    int j0 = c * CLEN;
    #pragma unroll 4
    for (int i = 0; i < CLEN; i++) {
        int j = j0 + i;
        int jm = (k >= 2) ? 4095 - j : j;
        int pos = (k & 1) ? ltmap(jm) : jm;
        float4 r4 = *(const float4*)(rec + j * 8);
        float Bs = rec[j * 8 + 4];
        float Cs = rec[j * 8 + 5];
        float x = xb[pos * 128 + d];
        float zz = fmaf(w4.x, r4.x, fmaf(w4.y, r4.y, fmaf(w4.z, r4.z, fmaf(w4.w, r4.w, bias))));
        float delta = sp(zz);
        float a = __expf(delta * Aval);
        float bb = delta * Bs * x;
        h = fmaf(a, h, bb);
        yplane[pos * 128 + d] = fmaf(h, Cs, Dval * x);
    }
}

// ------- K6: sum 4 planes + out LN * z + out_proj (128->64) + residual ------
__global__ void k6_out(const float* __restrict__ mag, const float* __restrict__ phase,
                       const float* __restrict__ onw, const float* __restrict__ onb,
                       const float* __restrict__ opw)
{
    __shared__ float sx[32][128];
    __shared__ float smu[32], srs[32];
    int row0 = blockIdx.x * 32;
    int e = row0 >> 15;
    int t = threadIdx.x;
    int r = t >> 3, c0 = (t & 7) * 16;
    #pragma unroll
    for (int i = 0; i < 4; i++) {
        size_t base = (size_t)(row0 + r) * 128 + c0 + 4 * i;
        float4 v0 = *(const float4*)&g_ys[base];
        float4 v1 = *(const float4*)&g_ys[base + (size_t)65536 * 128];
        float4 v2 = *(const float4*)&g_ys[base + (size_t)2 * 65536 * 128];
        float4 v3 = *(const float4*)&g_ys[base + (size_t)3 * 65536 * 128];
        sx[r][c0 + 4*i + 0] = v0.x + v1.x + v2.x + v3.x;
        sx[r][c0 + 4*i + 1] = v0.y + v1.y + v2.y + v3.y;
        sx[r][c0 + 4*i + 2] = v0.z + v1.z + v2.z + v3.z;
        sx[r][c0 + 4*i + 3] = v0.w + v1.w + v2.w + v3.w;
    }
    __syncthreads();
    if (t < 32) {
        float s = 0.f, s2 = 0.f;
        #pragma unroll 8
        for (int i = 0; i < 128; i++) { float v = sx[t][i]; s += v; s2 += v * v; }
        float mu = s * (1.f / 128.f);
        smu[t] = mu;
        srs[t] = rsqrtf(fmaxf(s2 * (1.f / 128.f) - mu * mu, 0.f) + 1e-5f);
    }
    __syncthreads();
    {
        float mu = smu[r], rs = srs[r];
        #pragma unroll
        for (int i = 0; i < 16; i++) {
            int c = c0 + i;
            float yn = (sx[r][c] - mu) * rs * onw[e * 128 + c] + onb[e * 128 + c];
            sx[r][c] = yn * g_z[(row0 + r) * 128 + c];
        }
    }
    __syncthreads();
    int c = t & 63, g = t >> 6;
    float acc[8];
    #pragma unroll
    for (int i = 0; i < 8; i++) acc[i] = 0.f;
    const float4* wp = (const float4*)&opw[(e * 64 + c) * 128];
    for (int ch = 0; ch < 32; ch++) {
        float4 w4 = wp[ch];
        #pragma unroll
        for (int rr = 0; rr < 8; rr++) {
            int r2 = g * 8 + rr;
            acc[rr] = fmaf(w4.x, sx[r2][ch*4+0], acc[rr]);
            acc[rr] = fmaf(w4.y, sx[r2][ch*4+1], acc[rr]);
            acc[rr] = fmaf(w4.z, sx[r2][ch*4+2], acc[rr]);
            acc[rr] = fmaf(w4.w, sx[r2][ch*4+3], acc[rr]);
        }
    }
    const float* xin = e ? phase : mag;
    int rl0 = row0 & 32767;
    #pragma unroll
    for (int rr = 0; rr < 8; rr++) {
        int r2 = g * 8 + rr;
        g_xres[(row0 + r2) * 64 + c] = acc[rr] + xin[(rl0 + r2) * 64 + c];
    }
}

// ---------------- K7: LN + fc1 + gelu + fc2 + residual ----------------------
__global__ void k7_mlp(const float* __restrict__ n2w, const float* __restrict__ n2b,
                       const float* __restrict__ f1w, const float* __restrict__ f1b,
                       const float* __restrict__ f2w, const float* __restrict__ f2b)
{
    __shared__ float sx[32][64];
    __shared__ float sh[32][256];
    __shared__ float smu[32], srs[32];
    int row0 = blockIdx.x * 32;
    int e = row0 >> 15;
    int t = threadIdx.x;
    int r = t >> 3, c0 = (t & 7) * 8;
    {
        float4 v0 = *(const float4*)&g_xres[(row0 + r) * 64 + c0];
        float4 v1 = *(const float4*)&g_xres[(row0 + r) * 64 + c0 + 4];
        sx[r][c0+0]=v0.x; sx[r][c0+1]=v0.y; sx[r][c0+2]=v0.z; sx[r][c0+3]=v0.w;
        sx[r][c0+4]=v1.x; sx[r][c0+5]=v1.y; sx[r][c0+6]=v1.z; sx[r][c0+7]=v1.w;
    }
    __syncthreads();
    if (t < 32) {
        float s = 0.f, s2 = 0.f;
        #pragma unroll
        for (int i = 0; i < 64; i++) { float v = sx[t][i]; s += v; s2 += v * v; }
        float mu = s * (1.f / 64.f);
        smu[t] = mu;
        srs[t] = rsqrtf(fmaxf(s2 * (1.f / 64.f) - mu * mu, 0.f) + 1e-5f);
    }
    __syncthreads();
    {
        float mu = smu[r], rs = srs[r];
        #pragma unroll
        for (int i = 0; i < 8; i++) {
            int c = c0 + i;
            sx[r][c] = (sx[r][c] - mu) * rs * n2w[e * 64 + c] + n2b[e * 64 + c];
        }
    }
    __syncthreads();
    {
        float acc[32];
        #pragma unroll
        for (int i = 0; i < 32; i++) acc[i] = 0.f;
        const float4* wp = (const float4*)&f1w[(e * 256 + t) * 64];
        for (int ch = 0; ch < 16; ch++) {
            float4 w4 = wp[ch];
            #pragma unroll
            for (int rr = 0; rr < 32; rr++) {
                acc[rr] = fmaf(w4.x, sx[rr][ch*4+0], acc[rr]);
                acc[rr] = fmaf(w4.y, sx[rr][ch*4+1], acc[rr]);
                acc[rr] = fmaf(w4.z, sx[rr][ch*4+2], acc[rr]);
                acc[rr] = fmaf(w4.w, sx[rr][ch*4+3], acc[rr]);
            }
        }
        float b1 = f1b[e * 256 + t];
        #pragma unroll
        for (int rr = 0; rr < 32; rr++)
            sh[rr][t] = geluf(acc[rr] + b1);
    }
    __syncthreads();
    {
        int c = t & 63, g = t >> 6;
        float acc[8];
        #pragma unroll
        for (int i = 0; i < 8; i++) acc[i] = 0.f;
        const float4* wp = (const float4*)&f2w[(e * 64 + c) * 256];
        for (int ch = 0; ch < 64; ch++) {
            float4 w4 = wp[ch];
            #pragma unroll
            for (int rr = 0; rr < 8; rr++) {
                int r2 = g * 8 + rr;
                acc[rr] = fmaf(w4.x, sh[r2][ch*4+0], acc[rr]);
                acc[rr] = fmaf(w4.y, sh[r2][ch*4+1], acc[rr]);
                acc[rr] = fmaf(w4.z, sh[r2][ch*4+2], acc[rr]);
                acc[rr] = fmaf(w4.w, sh[r2][ch*4+3], acc[rr]);
            }
        }
        float b2 = f2b[e * 64 + c];
        #pragma unroll
        for (int rr = 0; rr < 8; rr++) {
            int r2 = g * 8 + rr;
            g_mlp[(row0 + r2) * 64 + c] = g_xres[(row0 + r2) * 64 + c] + acc[rr] + b2;
        }
    }
}

// ---------------- K8: sum streams, duplicate output -------------------------
__global__ void k8_final(float* __restrict__ out)
{
    int i = blockIdx.x * 256 + threadIdx.x;   // 0..2097151
    float s = g_mlp[i] + g_mlp[i + 2097152];
    out[i] = s;
    out[i + 2097152] = s;
}

// ---------------- launch ----------------------------------------------------
extern "C" void kernel_launch(void* const* d_in, const int* in_sizes, int n_in,
                              void* d_out, int out_size)
{
    const float* mag   = (const float*)d_in[0];
    const float* phase = (const float*)d_in[1];
    const float* n1w   = (const float*)d_in[2];
    const float* n1b   = (const float*)d_in[3];
    const float* ipw   = (const float*)d_in[4];
    const float* cvw   = (const float*)d_in[5];
    const float* xpw   = (const float*)d_in[6];
    const float* dtw   = (const float*)d_in[7];
    const float* dtb   = (const float*)d_in[8];
    const float* alg   = (const float*)d_in[9];
    const float* dsv   = (const float*)d_in[10];
    const float* onw   = (const float*)d_in[11];
    const float* onb   = (const float*)d_in[12];
    const float* opw   = (const float*)d_in[13];
    const float* n2w   = (const float*)d_in[14];
    const float* n2b   = (const float*)d_in[15];
    const float* f1w   = (const float*)d_in[16];
    const float* f1b   = (const float*)d_in[17];
    const float* f2w   = (const float*)d_in[18];
    const float* f2b   = (const float*)d_in[19];

    k1_ln_inproj<<<2048, 256>>>(mag, phase, n1w, n1b, ipw);
    k2_conv<<<65536, 128>>>(cvw);
    k3_xdbl<<<4096, 256>>>(xpw);
    k4a_scan_partial<<<2048, 128>>>(dtw, dtb, alg);
    k4b_scan_prefix<<<64, 128>>>();
    k4c_scan_final<<<2048, 128>>>(dtw, dtb, alg, dsv);
    k6_out<<<2048, 256>>>(mag, phase, onw, onb, opw);
    k7_mlp<<<2048, 256>>>(n2w, n2b, f1w, f1b, f2w, f2b);
    k8_final<<<8192, 256>>>((float*)d_out);
}